// round 3
// baseline (speedup 1.0000x reference)
#include <cuda_runtime.h>

#define NOUT 48
#define CIN 384
#define NPIX 35200       // ny*nx = 200*176 (even)
#define NB 4
#define TOTAL_PIX (NB * NPIX)   // 140800

// ---- packed f32x2 helpers (sm_103a) ----
__device__ __forceinline__ unsigned long long pack2(float lo, float hi) {
    unsigned long long r;
    asm("mov.b64 %0, {%1, %2};" : "=l"(r) : "f"(lo), "f"(hi));
    return r;
}
__device__ __forceinline__ void unpack2(unsigned long long v, float& lo, float& hi) {
    asm("mov.b64 {%0, %1}, %2;" : "=f"(lo), "=f"(hi) : "l"(v));
}
__device__ __forceinline__ void ffma2(unsigned long long& d,
                                      unsigned long long a,
                                      unsigned long long b) {
    asm("fma.rn.f32x2 %0, %1, %2, %0;" : "+l"(d) : "l"(a), "l"(b));
}

extern __shared__ float s_buf[];   // [CIN*NOUT] transposed weights, then [NOUT] bias

__global__ __launch_bounds__(128)
void proposal_kernel(const float* __restrict__ feat,
                     const float* __restrict__ Wc,
                     const float* __restrict__ bc,
                     const float* __restrict__ Wr,
                     const float* __restrict__ br,
                     float* __restrict__ out)
{
    float* ws = s_buf;               // ws[c*48 + o] = W[o][c], o<6 -> Wc, else Wr
    float* bs = s_buf + CIN * NOUT;  // bs[o]

    const int tid = threadIdx.x;

    // cooperative transposed weight load (one-time per block; weights tiny & L2-hot)
    for (int i = tid; i < CIN * NOUT; i += blockDim.x) {
        const int c = i / NOUT;
        const int o = i % NOUT;
        ws[i] = (o < 6) ? Wc[o * CIN + c] : Wr[(o - 6) * CIN + c];
    }
    if (tid < NOUT) bs[tid] = (tid < 6) ? bc[tid] : br[tid - 6];
    __syncthreads();

    // each thread owns an ADJACENT pixel pair (p0, p0+1); NPIX even -> never crosses batch
    const int gt = blockIdx.x * blockDim.x + tid;
    const int g0 = 2 * gt;               // global pixel of lane's first pixel
    const int b  = g0 / NPIX;
    const int p0 = g0 % NPIX;            // even

    // 24 packed accumulators per pixel: acc[q] = outputs (2q, 2q+1)
    unsigned long long accA[NOUT / 2], accB[NOUT / 2];
#pragma unroll
    for (int q = 0; q < NOUT / 2; q++) {
        const unsigned long long bq = pack2(bs[2 * q], bs[2 * q + 1]);
        accA[q] = bq;
        accB[q] = bq;
    }

    const float* fb = feat + (long)b * CIN * NPIX + p0;

#pragma unroll 2
    for (int c = 0; c < CIN; c++) {
        const float2 f2 = *(const float2*)(fb + (long)c * NPIX);  // LDG.64, 8B-aligned
        const unsigned long long faA = pack2(f2.x, f2.x);
        const unsigned long long faB = pack2(f2.y, f2.y);
        const ulonglong2* wrow = (const ulonglong2*)(ws + c * NOUT);  // broadcast LDS.128
#pragma unroll
        for (int q2 = 0; q2 < 12; q2++) {
            const ulonglong2 w2 = wrow[q2];   // channels (4q2..4q2+3)
            ffma2(accA[2 * q2 + 0], faA, w2.x);
            ffma2(accA[2 * q2 + 1], faA, w2.y);
            ffma2(accB[2 * q2 + 0], faB, w2.x);
            ffma2(accB[2 * q2 + 1], faB, w2.y);
        }
    }

    // ---- cls: out[(b*6 + o)*NPIX + p]; pixels adjacent -> float2 stores (p0 even) ----
#pragma unroll
    for (int q = 0; q < 3; q++) {
        float a_lo, a_hi, b_lo, b_hi;
        unpack2(accA[q], a_lo, a_hi);   // pixel p0: outputs 2q, 2q+1
        unpack2(accB[q], b_lo, b_hi);   // pixel p0+1
        float2 v0 = make_float2(a_lo, b_lo);
        float2 v1 = make_float2(a_hi, b_hi);
        *(float2*)(out + ((long)b * 6 + (2 * q + 0)) * NPIX + p0) = v0;
        *(float2*)(out + ((long)b * 6 + (2 * q + 1)) * NPIX + p0) = v1;
    }

    // ---- reg: permuted layout (B, 3, 2, ny, nx, 7) ----
    // reg_raw channel o_r = c3*14 + d*2 + y  (combined o = 6 + o_r)
    // packed pair q = 3 + c3*7 + d holds (y=0 in lo, y=1 in hi)
    float* outr = out + (long)NB * 6 * NPIX;
#pragma unroll
    for (int c3 = 0; c3 < 3; c3++) {
        const long b00 = ((((long)b * 3 + c3) * 2 + 0) * NPIX + p0) * 7;      // pix p0, y=0
        const long b01 = ((((long)b * 3 + c3) * 2 + 1) * NPIX + p0) * 7;      // pix p0, y=1
#pragma unroll
        for (int d = 0; d < 7; d++) {
            float a_lo, a_hi, b_lo, b_hi;
            unpack2(accA[3 + c3 * 7 + d], a_lo, a_hi);
            unpack2(accB[3 + c3 * 7 + d], b_lo, b_hi);
            outr[b00 + d]     = a_lo;   // pixel p0,   y=0
            outr[b01 + d]     = a_hi;   // pixel p0,   y=1
            outr[b00 + 7 + d] = b_lo;   // pixel p0+1, y=0
            outr[b01 + 7 + d] = b_hi;   // pixel p0+1, y=1
        }
    }
}

extern "C" void kernel_launch(void* const* d_in, const int* in_sizes, int n_in,
                              void* d_out, int out_size)
{
    const float* feat = (const float*)d_in[0];
    const float* Wc   = (const float*)d_in[1];
    const float* bc   = (const float*)d_in[2];
    const float* Wr   = (const float*)d_in[3];
    const float* br   = (const float*)d_in[4];
    float* out = (float*)d_out;

    const int smem_bytes = (CIN * NOUT + NOUT) * (int)sizeof(float);  // 73920 B
    cudaFuncSetAttribute(proposal_kernel,
                         cudaFuncAttributeMaxDynamicSharedMemorySize, smem_bytes);

    const int threads = 128;
    const int blocks  = TOTAL_PIX / (threads * 2);   // 550, exact
    proposal_kernel<<<blocks, threads, smem_bytes>>>(feat, Wc, bc, Wr, br, out);
}

// round 4
// speedup vs baseline: 1.4196x; 1.4196x over previous
#include <cuda_runtime.h>

#define NOUT 48
#define CIN 384
#define NPIX 35200       // ny*nx = 200*176 (multiple of 4)
#define NB 4
#define TOTAL_PIX (NB * NPIX)   // 140800 = 550 * 256

typedef unsigned long long u64;

// ---- packed f32x2 helpers (sm_103a) ----
__device__ __forceinline__ u64 pack2(float lo, float hi) {
    u64 r;
    asm("mov.b64 %0, {%1, %2};" : "=l"(r) : "f"(lo), "f"(hi));
    return r;
}
__device__ __forceinline__ void unpack2(u64 v, float& lo, float& hi) {
    asm("mov.b64 {%0, %1}, %2;" : "=f"(lo), "=f"(hi) : "l"(v));
}
__device__ __forceinline__ void ffma2(u64& d, u64 a, u64 b) {
    asm("fma.rn.f32x2 %0, %1, %2, %0;" : "+l"(d) : "l"(a), "l"(b));
}

extern __shared__ float s_buf[];   // ws[CIN][48] transposed weights, then bs[48]

__global__ __launch_bounds__(128, 3)
void proposal_kernel(const float* __restrict__ feat,
                     const float* __restrict__ Wc,
                     const float* __restrict__ bc,
                     const float* __restrict__ Wr,
                     const float* __restrict__ br,
                     float* __restrict__ out)
{
    float* ws = s_buf;               // ws[c*48 + o] = W[o][c]
    float* bs = s_buf + CIN * NOUT;

    const int tid = threadIdx.x;

    for (int i = tid; i < CIN * NOUT; i += blockDim.x) {
        const int c = i / NOUT;
        const int o = i % NOUT;
        ws[i] = (o < 6) ? Wc[o * CIN + c] : Wr[(o - 6) * CIN + c];
    }
    if (tid < NOUT) bs[tid] = (tid < 6) ? bc[tid] : br[tid - 6];
    __syncthreads();

    // 4 warps: (pixel-group pg 0..1) x (output-half ty 0..1)
    const int lane = tid & 31;
    const int warp = tid >> 5;
    const int ty   = warp & 1;        // outputs [24*ty, 24*ty+24)
    const int pg   = warp >> 1;       // pixel sub-tile

    // this thread: 4 consecutive pixels (block tile = 256 pixels)
    const int g0 = blockIdx.x * 256 + pg * 128 + lane * 4;  // multiple of 4
    const int b  = g0 / NPIX;         // 4-pixel group never crosses batch (NPIX%4==0)
    const int p0 = g0 % NPIX;

    // acc[pix][qp]: outputs (24*ty + 2*qp, +1) packed in f32x2
    u64 acc[4][12];
#pragma unroll
    for (int qp = 0; qp < 12; qp++) {
        const u64 bq = pack2(bs[24 * ty + 2 * qp], bs[24 * ty + 2 * qp + 1]);
#pragma unroll
        for (int px = 0; px < 4; px++) acc[px][qp] = bq;
    }

    const float* fb = feat + (long)b * CIN * NPIX + p0;
    const float* wbase = ws + 24 * ty;

#pragma unroll 4
    for (int c = 0; c < CIN; c++) {
        const float4 f4 = *(const float4*)(fb + (long)c * NPIX);   // LDG.128 coalesced
        const u64 fA = pack2(f4.x, f4.x);
        const u64 fB = pack2(f4.y, f4.y);
        const u64 fC = pack2(f4.z, f4.z);
        const u64 fD = pack2(f4.w, f4.w);
        const ulonglong2* wr = (const ulonglong2*)(wbase + c * NOUT);  // 6x LDS.128 broadcast
#pragma unroll
        for (int qq = 0; qq < 6; qq++) {
            const ulonglong2 w2 = wr[qq];   // outputs (24ty+4qq .. +3)
            ffma2(acc[0][2 * qq + 0], fA, w2.x);
            ffma2(acc[0][2 * qq + 1], fA, w2.y);
            ffma2(acc[1][2 * qq + 0], fB, w2.x);
            ffma2(acc[1][2 * qq + 1], fB, w2.y);
            ffma2(acc[2][2 * qq + 0], fC, w2.x);
            ffma2(acc[2][2 * qq + 1], fC, w2.y);
            ffma2(acc[3][2 * qq + 0], fD, w2.x);
            ffma2(acc[3][2 * qq + 1], fD, w2.y);
        }
    }

    // ================= epilogue =================
    // global packed pair Q = 12*ty + qp covers outputs (2Q, 2Q+1)
    // Q < 3        -> cls channels (2Q, 2Q+1)
    // Q >= 3       -> reg pair r = Q-3: c3 = r/7, d = r%7, lo=y0, hi=y1

    if (ty == 0) {
        // cls: out[(b*6 + o)*NPIX + p], 4 adjacent pixels -> float4 stores
#pragma unroll
        for (int q = 0; q < 3; q++) {
            float lo0, hi0, lo1, hi1, lo2, hi2, lo3, hi3;
            unpack2(acc[0][q], lo0, hi0);
            unpack2(acc[1][q], lo1, hi1);
            unpack2(acc[2][q], lo2, hi2);
            unpack2(acc[3][q], lo3, hi3);
            *(float4*)(out + ((long)b * 6 + 2 * q + 0) * NPIX + p0) =
                make_float4(lo0, lo1, lo2, lo3);
            *(float4*)(out + ((long)b * 6 + 2 * q + 1) * NPIX + p0) =
                make_float4(hi0, hi1, hi2, hi3);
        }
    }

    // reg: layout (B, 3, 2, ny, nx, 7)
    float* outr = out + (long)NB * 6 * NPIX;
#pragma unroll
    for (int j = 0; j < 12; j++) {
        const int Q = 12 * ty + j;
        if (Q < 3) continue;                 // compile-time pruned (cls pairs)
        const int r  = Q - 3;
        const int c3 = r / 7;
        const int d  = r % 7;
        const long base0 = ((((long)b * 3 + c3) * 2 + 0) * NPIX + p0) * 7 + d;  // y=0
        const long base1 = ((((long)b * 3 + c3) * 2 + 1) * NPIX + p0) * 7 + d;  // y=1
#pragma unroll
        for (int px = 0; px < 4; px++) {
            float lo, hi;
            unpack2(acc[px][j], lo, hi);
            outr[base0 + 7 * px] = lo;
            outr[base1 + 7 * px] = hi;
        }
    }
}

extern "C" void kernel_launch(void* const* d_in, const int* in_sizes, int n_in,
                              void* d_out, int out_size)
{
    const float* feat = (const float*)d_in[0];
    const float* Wc   = (const float*)d_in[1];
    const float* bc   = (const float*)d_in[2];
    const float* Wr   = (const float*)d_in[3];
    const float* br   = (const float*)d_in[4];
    float* out = (float*)d_out;

    const int smem_bytes = (CIN * NOUT + NOUT) * (int)sizeof(float);  // 73920 B
    cudaFuncSetAttribute(proposal_kernel,
                         cudaFuncAttributeMaxDynamicSharedMemorySize, smem_bytes);

    const int threads = 128;                       // 4 warps: 2 pixel-groups x 2 out-halves
    const int blocks  = TOTAL_PIX / 256;           // 550, exact (256 pixels per block)
    proposal_kernel<<<blocks, threads, smem_bytes>>>(feat, Wc, bc, Wr, br, out);
}